// round 2
// baseline (speedup 1.0000x reference)
#include <cuda_runtime.h>
#include <cuda_bf16.h>
#include <cstdint>

#define N_NODES 100000
#define E_MAX   1600000

// ---------------- device scratch (static; no dynamic allocation) ----------------
__device__ int   g_is64;
__device__ int   g_deg[N_NODES];
__device__ int   g_offs[N_NODES + 1];
__device__ int   g_cursor[N_NODES];
__device__ int   g_src_sorted[E_MAX];
__device__ float g_agg[(size_t)N_NODES * 128];
__device__ float g_h[(size_t)N_NODES * 128];

// ---------------- edge dtype detection (int32 vs int64) ----------------
// If edge_index is int64 with values < 2^31 (node ids < 100000), every odd
// 32-bit word is 0. If int32, odd words are real node ids (~never all zero).
__global__ void detect_kernel(const int* __restrict__ ei32, int n_words) {
    if (threadIdx.x == 0 && blockIdx.x == 0) {
        int zeros = 0;
        int lim = n_words < 128 ? n_words : 128;
        for (int i = 1; i < lim; i += 2)
            if (ei32[i] == 0) zeros++;
        g_is64 = (zeros > 48) ? 1 : 0;
    }
}

// ---------------- CSR-by-dst build ----------------
__global__ void zero_deg_kernel() {
    int i = blockIdx.x * blockDim.x + threadIdx.x;
    if (i < N_NODES) g_deg[i] = 0;
}

__device__ __forceinline__ int load_idx(const void* ei, size_t pos) {
    if (g_is64) return (int)((const long long*)ei)[pos];
    return ((const int*)ei)[pos];
}

__global__ void hist_kernel(const void* __restrict__ ei, int E) {
    int e = blockIdx.x * blockDim.x + threadIdx.x;
    if (e < E) {
        int d = load_idx(ei, (size_t)E + e);
        if ((unsigned)d < (unsigned)N_NODES) atomicAdd(&g_deg[d], 1);
    }
}

// single block / 1024 threads: exclusive scan deg -> offs (+ cursor copy)
__global__ void scan_kernel() {
    __shared__ int s_woff[32];
    __shared__ int s_total;
    int tid = threadIdx.x, lane = tid & 31, wid = tid >> 5;
    int carry = 0;
    for (int base = 0; base < N_NODES; base += 1024) {
        int i = base + tid;
        int v = (i < N_NODES) ? g_deg[i] : 0;
        int inc = v;
#pragma unroll
        for (int o = 1; o < 32; o <<= 1) {
            int t = __shfl_up_sync(0xffffffffu, inc, o);
            if (lane >= o) inc += t;
        }
        if (lane == 31) s_woff[wid] = inc;
        __syncthreads();
        if (wid == 0) {
            int ws = s_woff[lane];
            int wi = ws;
#pragma unroll
            for (int o = 1; o < 32; o <<= 1) {
                int t = __shfl_up_sync(0xffffffffu, wi, o);
                if (lane >= o) wi += t;
            }
            s_woff[lane] = wi - ws;  // exclusive warp offsets
        }
        __syncthreads();
        int excl = s_woff[wid] + inc - v;
        if (tid == 1023) s_total = excl + v;
        if (i < N_NODES) {
            int o = carry + excl;
            g_offs[i]   = o;
            g_cursor[i] = o;
        }
        __syncthreads();
        carry += s_total;
    }
    if (tid == 0) g_offs[N_NODES] = carry;
}

__global__ void scatter_kernel(const void* __restrict__ ei, int E) {
    int e = blockIdx.x * blockDim.x + threadIdx.x;
    if (e < E) {
        int d = load_idx(ei, (size_t)E + e);
        int s = load_idx(ei, (size_t)e);
        if ((unsigned)d < (unsigned)N_NODES && (unsigned)s < (unsigned)N_NODES) {
            int p = atomicAdd(&g_cursor[d], 1);
            g_src_sorted[p] = s;
        }
    }
}

// ---------------- segment mean aggregation (warp per node, no float atomics) ----
__global__ void agg1_kernel(const float* __restrict__ x) {      // 64 feats -> g_agg
    int w = (blockIdx.x * blockDim.x + threadIdx.x) >> 5;
    if (w >= N_NODES) return;
    int lane = threadIdx.x & 31;
    int beg = g_offs[w], end = g_offs[w + 1];
    float inv = 1.0f / (float)max(end - beg, 1);
    float ax = 0.f, ay = 0.f;
    for (int eb = beg; eb < end; eb += 32) {
        int n = min(32, end - eb);
        int s = (lane < n) ? g_src_sorted[eb + lane] : 0;
        for (int t = 0; t < n; t++) {
            int ss = __shfl_sync(0xffffffffu, s, t);
            float2 v = *(const float2*)&x[(size_t)ss * 64 + lane * 2];
            ax += v.x; ay += v.y;
        }
    }
    float2 o; o.x = ax * inv; o.y = ay * inv;
    *(float2*)&g_agg[(size_t)w * 64 + lane * 2] = o;
}

__global__ void agg2_kernel() {                                  // 128 feats (g_h) -> g_agg
    int w = (blockIdx.x * blockDim.x + threadIdx.x) >> 5;
    if (w >= N_NODES) return;
    int lane = threadIdx.x & 31;
    int beg = g_offs[w], end = g_offs[w + 1];
    float inv = 1.0f / (float)max(end - beg, 1);
    float ax = 0.f, ay = 0.f, az = 0.f, aw = 0.f;
    for (int eb = beg; eb < end; eb += 32) {
        int n = min(32, end - eb);
        int s = (lane < n) ? g_src_sorted[eb + lane] : 0;
        for (int t = 0; t < n; t++) {
            int ss = __shfl_sync(0xffffffffu, s, t);
            float4 v = *(const float4*)&g_h[(size_t)ss * 128 + lane * 4];
            ax += v.x; ay += v.y; az += v.z; aw += v.w;
        }
    }
    float4 o; o.x = ax * inv; o.y = ay * inv; o.z = az * inv; o.w = aw * inv;
    *(float4*)&g_agg[(size_t)w * 128 + lane * 4] = o;
}

// ---------------- fused dual GEMM: out = act( g_agg@Wl^T + X@Wr^T + b ) ----------
// LAYER==1: X = external x, out = g_h, RELU. LAYER==2: X = g_h, out = external.
template <int K, bool RELU, int LAYER>
__global__ __launch_bounds__(256) void gemm_kernel(
    const float* __restrict__ Xext,
    const float* __restrict__ Wl, const float* __restrict__ Wr,
    const float* __restrict__ b, float* __restrict__ out_ext, int M)
{
    constexpr int BM = 64, BN = 128, BK = 16, KT = 2 * K;
    __shared__ __align__(16) float Fs[BK][BM];
    __shared__ __align__(16) float Ws[BK][BN];

    const float* A = g_agg;
    const float* X = (LAYER == 1) ? Xext : g_h;
    float*       out = (LAYER == 1) ? g_h : out_ext;

    int tid = threadIdx.x;
    int cg  = tid & 31;          // cols cg*4..cg*4+3
    int rg  = tid >> 5;          // rows rg*8..rg*8+7
    int row0 = blockIdx.x * BM;

    float acc[8][4];
#pragma unroll
    for (int r = 0; r < 8; r++)
#pragma unroll
        for (int c = 0; c < 4; c++) acc[r][c] = 0.f;

    int f_r = tid >> 2;          // 0..63
    int f_k = (tid & 3) << 2;    // 0,4,8,12
    int w_j = tid >> 2;          // 0..63 (also +64)

    for (int k0 = 0; k0 < KT; k0 += BK) {
        const float* Fsrc; const float* Wsrc; int kk;
        if (k0 < K) { Fsrc = A; Wsrc = Wl; kk = k0; }
        else        { Fsrc = X; Wsrc = Wr; kk = k0 - K; }

        float4 fv = make_float4(0.f, 0.f, 0.f, 0.f);
        int grow = row0 + f_r;
        if (grow < M) fv = *(const float4*)&Fsrc[(size_t)grow * K + kk + f_k];
        float4 wv0 = *(const float4*)&Wsrc[(size_t)w_j * K + kk + f_k];
        float4 wv1 = *(const float4*)&Wsrc[(size_t)(w_j + 64) * K + kk + f_k];

        __syncthreads();
        Fs[f_k + 0][f_r] = fv.x; Fs[f_k + 1][f_r] = fv.y;
        Fs[f_k + 2][f_r] = fv.z; Fs[f_k + 3][f_r] = fv.w;
        Ws[f_k + 0][w_j] = wv0.x; Ws[f_k + 1][w_j] = wv0.y;
        Ws[f_k + 2][w_j] = wv0.z; Ws[f_k + 3][w_j] = wv0.w;
        Ws[f_k + 0][w_j + 64] = wv1.x; Ws[f_k + 1][w_j + 64] = wv1.y;
        Ws[f_k + 2][w_j + 64] = wv1.z; Ws[f_k + 3][w_j + 64] = wv1.w;
        __syncthreads();

#pragma unroll
        for (int k = 0; k < BK; k++) {
            float4 wreg = *(const float4*)&Ws[k][cg * 4];
            float4 f0   = *(const float4*)&Fs[k][rg * 8];
            float4 f1   = *(const float4*)&Fs[k][rg * 8 + 4];
            float fr[8] = { f0.x, f0.y, f0.z, f0.w, f1.x, f1.y, f1.z, f1.w };
            float wc[4] = { wreg.x, wreg.y, wreg.z, wreg.w };
#pragma unroll
            for (int r = 0; r < 8; r++)
#pragma unroll
                for (int c = 0; c < 4; c++)
                    acc[r][c] += fr[r] * wc[c];
        }
    }

    float4 bias = *(const float4*)&b[cg * 4];
#pragma unroll
    for (int r = 0; r < 8; r++) {
        int grow = row0 + rg * 8 + r;
        if (grow < M) {
            float4 o;
            o.x = acc[r][0] + bias.x;
            o.y = acc[r][1] + bias.y;
            o.z = acc[r][2] + bias.z;
            o.w = acc[r][3] + bias.w;
            if (RELU) {
                o.x = fmaxf(o.x, 0.f); o.y = fmaxf(o.y, 0.f);
                o.z = fmaxf(o.z, 0.f); o.w = fmaxf(o.w, 0.f);
            }
            *(float4*)&out[(size_t)grow * 128 + cg * 4] = o;
        }
    }
}

// ---------------- entry point ----------------
extern "C" void kernel_launch(void* const* d_in, const int* in_sizes, int n_in,
                              void* d_out, int out_size)
{
    (void)n_in; (void)out_size;
    const float* x   = (const float*)d_in[0];
    const void*  ei  = d_in[1];
    const float* W1l = (const float*)d_in[2];
    const float* W1r = (const float*)d_in[3];
    const float* b1  = (const float*)d_in[4];
    const float* W2l = (const float*)d_in[5];
    const float* W2r = (const float*)d_in[6];
    const float* b2  = (const float*)d_in[7];
    float*       out = (float*)d_out;

    int E = in_sizes[1] / 2;
    if (E > E_MAX) E = E_MAX;
    const int M = N_NODES;

    detect_kernel<<<1, 32>>>((const int*)ei, in_sizes[1]);
    zero_deg_kernel<<<(N_NODES + 255) / 256, 256>>>();
    hist_kernel<<<(E + 255) / 256, 256>>>(ei, E);
    scan_kernel<<<1, 1024>>>();
    scatter_kernel<<<(E + 255) / 256, 256>>>(ei, E);

    int agg_blocks = (N_NODES * 32 + 255) / 256;   // warp per node
    int gemm_blocks = (M + 63) / 64;

    agg1_kernel<<<agg_blocks, 256>>>(x);
    gemm_kernel<64, true, 1><<<gemm_blocks, 256>>>(x, W1l, W1r, b1, nullptr, M);
    agg2_kernel<<<agg_blocks, 256>>>();
    gemm_kernel<128, false, 2><<<gemm_blocks, 256>>>(nullptr, W2l, W2r, b2, out, M);
}

// round 4
// speedup vs baseline: 1.5488x; 1.5488x over previous
#include <cuda_runtime.h>
#include <cuda_bf16.h>
#include <cstdint>

#define N_NODES 100000
#define E_MAX   1600000
#define NPART   98          // ceil(100000/1024)

// ---------------- device scratch (static; no dynamic allocation) ----------------
__device__ int   g_is64;
__device__ int   g_deg[N_NODES];
__device__ int   g_offs[N_NODES + 1];
__device__ int   g_cursor[N_NODES];
__device__ int   g_part[NPART];
__device__ int   g_src_sorted[E_MAX];
__device__ float g_agg[(size_t)N_NODES * 128];
__device__ float g_h[(size_t)N_NODES * 128];
// bf16 split operands (A = [agg | x] concatenated, stride = KT)
__device__ __nv_bfloat16 g_ah[(size_t)N_NODES * 256];
__device__ __nv_bfloat16 g_al[(size_t)N_NODES * 256];
__device__ __nv_bfloat16 g_wh[128 * 256];
__device__ __nv_bfloat16 g_wlo[128 * 256];

// ==================== PTX helpers (family-portable: ldmatrix + mma.sync) =========
__device__ __forceinline__ uint32_t smem_u32(const void* p) {
    uint32_t a;
    asm("{ .reg .u64 t; cvta.to.shared.u64 t, %1; cvt.u32.u64 %0, t; }" : "=r"(a) : "l"(p));
    return a;
}
#define LDSM_X4(r0, r1, r2, r3, addr)                                           \
    asm volatile("ldmatrix.sync.aligned.m8n8.x4.shared.b16 {%0,%1,%2,%3}, [%4];" \
                 : "=r"(r0), "=r"(r1), "=r"(r2), "=r"(r3) : "r"(addr))
#define MMA16816(c, a, b)                                                        \
    asm volatile("mma.sync.aligned.m16n8k16.row.col.f32.bf16.bf16.f32 "          \
                 "{%0,%1,%2,%3}, {%4,%5,%6,%7}, {%8,%9}, {%0,%1,%2,%3};"         \
                 : "+f"((c)[0]), "+f"((c)[1]), "+f"((c)[2]), "+f"((c)[3])        \
                 : "r"((a)[0]), "r"((a)[1]), "r"((a)[2]), "r"((a)[3]),           \
                   "r"((b)[0]), "r"((b)[1]))

// ==================== edge dtype detection ====================
__global__ void detect_kernel(const int* __restrict__ ei32, int n_words) {
    int lane = threadIdx.x;
    int idx = 1 + 2 * lane;
    int z = (idx < n_words && ei32[idx] == 0) ? 1 : 0;
    unsigned m = __ballot_sync(0xffffffffu, z);
    if (lane == 0) g_is64 = (__popc(m) > 24) ? 1 : 0;
}

// ==================== CSR build ====================
__global__ void zero_deg_kernel() {
    int i = blockIdx.x * blockDim.x + threadIdx.x;
    if (i < N_NODES) g_deg[i] = 0;
}
__device__ __forceinline__ int load_idx(const void* ei, size_t pos) {
    if (g_is64) return (int)((const long long*)ei)[pos];
    return ((const int*)ei)[pos];
}
__global__ void hist_kernel(const void* __restrict__ ei, int E) {
    int e = blockIdx.x * blockDim.x + threadIdx.x;
    if (e < E) {
        int d = load_idx(ei, (size_t)E + e);
        if ((unsigned)d < (unsigned)N_NODES) atomicAdd(&g_deg[d], 1);
    }
}
__global__ void scan_part_kernel() {
    __shared__ int s_woff[32];
    int tid = threadIdx.x, lane = tid & 31, wid = tid >> 5;
    int i = blockIdx.x * 1024 + tid;
    int v = (i < N_NODES) ? g_deg[i] : 0;
    int inc = v;
#pragma unroll
    for (int o = 1; o < 32; o <<= 1) {
        int t = __shfl_up_sync(0xffffffffu, inc, o);
        if (lane >= o) inc += t;
    }
    if (lane == 31) s_woff[wid] = inc;
    __syncthreads();
    if (wid == 0) {
        int ws = s_woff[lane];
        int wi = ws;
#pragma unroll
        for (int o = 1; o < 32; o <<= 1) {
            int t = __shfl_up_sync(0xffffffffu, wi, o);
            if (lane >= o) wi += t;
        }
        s_woff[lane] = wi - ws;
    }
    __syncthreads();
    int excl = s_woff[wid] + inc - v;
    if (i < N_NODES) g_offs[i] = excl;
    if (tid == 1023) g_part[blockIdx.x] = excl + v;
}
__global__ void scan_part2_kernel() {    // 1 block, 128 threads (NPART <= 128)
    __shared__ int sw[4];
    int t = threadIdx.x, lane = t & 31, w = t >> 5;
    int v = (t < NPART) ? g_part[t] : 0;
    int inc = v;
#pragma unroll
    for (int o = 1; o < 32; o <<= 1) {
        int x = __shfl_up_sync(0xffffffffu, inc, o);
        if (lane >= o) inc += x;
    }
    if (lane == 31) sw[w] = inc;
    __syncthreads();
    int woff = 0;
    for (int k = 0; k < w; k++) woff += sw[k];
    int excl = woff + inc - v;
    if (t < NPART) g_part[t] = excl;
    if (t == NPART - 1) g_offs[N_NODES] = excl + v;
}
__global__ void scan_add_kernel() {
    int i = blockIdx.x * 1024 + threadIdx.x;
    if (i < N_NODES) {
        int o = g_offs[i] + g_part[blockIdx.x];
        g_offs[i] = o;
        g_cursor[i] = o;
    }
}
__global__ void scatter_kernel(const void* __restrict__ ei, int E) {
    int e = blockIdx.x * blockDim.x + threadIdx.x;
    if (e < E) {
        int d = load_idx(ei, (size_t)E + e);
        int s = load_idx(ei, (size_t)e);
        if ((unsigned)d < (unsigned)N_NODES && (unsigned)s < (unsigned)N_NODES) {
            int p = atomicAdd(&g_cursor[d], 1);
            g_src_sorted[p] = s;
        }
    }
}

// ==================== segment mean aggregation ====================
__global__ void agg1_kernel(const float* __restrict__ x) {       // 64 feats -> g_agg
    int w = (blockIdx.x * blockDim.x + threadIdx.x) >> 5;
    if (w >= N_NODES) return;
    int lane = threadIdx.x & 31;
    int beg = g_offs[w], end = g_offs[w + 1];
    float inv = 1.0f / (float)max(end - beg, 1);
    float ax = 0.f, ay = 0.f;
    for (int eb = beg; eb < end; eb += 32) {
        int n = min(32, end - eb);
        int s = (lane < n) ? g_src_sorted[eb + lane] : 0;
        for (int t = 0; t < n; t++) {
            int ss = __shfl_sync(0xffffffffu, s, t);
            float2 v = *(const float2*)&x[(size_t)ss * 64 + lane * 2];
            ax += v.x; ay += v.y;
        }
    }
    float2 o; o.x = ax * inv; o.y = ay * inv;
    *(float2*)&g_agg[(size_t)w * 64 + lane * 2] = o;
}
__global__ void agg2_kernel() {                                   // 128 feats (g_h) -> g_agg
    int w = (blockIdx.x * blockDim.x + threadIdx.x) >> 5;
    if (w >= N_NODES) return;
    int lane = threadIdx.x & 31;
    int beg = g_offs[w], end = g_offs[w + 1];
    float inv = 1.0f / (float)max(end - beg, 1);
    float ax = 0.f, ay = 0.f, az = 0.f, aw = 0.f;
    for (int eb = beg; eb < end; eb += 32) {
        int n = min(32, end - eb);
        int s = (lane < n) ? g_src_sorted[eb + lane] : 0;
        for (int t = 0; t < n; t++) {
            int ss = __shfl_sync(0xffffffffu, s, t);
            float4 v = *(const float4*)&g_h[(size_t)ss * 128 + lane * 4];
            ax += v.x; ay += v.y; az += v.z; aw += v.w;
        }
    }
    float4 o; o.x = ax * inv; o.y = ay * inv; o.z = az * inv; o.w = aw * inv;
    *(float4*)&g_agg[(size_t)w * 128 + lane * 4] = o;
}

// ==================== bf16 hi/lo conversion ====================
__device__ __forceinline__ void split4(float4 v, __nv_bfloat16* h, __nv_bfloat16* l) {
    h[0] = __float2bfloat16(v.x); l[0] = __float2bfloat16(v.x - __bfloat162float(h[0]));
    h[1] = __float2bfloat16(v.y); l[1] = __float2bfloat16(v.y - __bfloat162float(h[1]));
    h[2] = __float2bfloat16(v.z); l[2] = __float2bfloat16(v.z - __bfloat162float(h[2]));
    h[3] = __float2bfloat16(v.w); l[3] = __float2bfloat16(v.w - __bfloat162float(h[3]));
}
__global__ void convert_a1_kernel(const float* __restrict__ x) {   // [agg1(64)|x(64)] -> stride 128
    long idx = (long)blockIdx.x * blockDim.x + threadIdx.x;        // per float4
    const long total = (long)N_NODES * 32;
    if (idx >= total) return;
    int m = (int)(idx >> 5);
    int c4 = ((int)idx & 31) * 4;
    float4 v = (c4 < 64) ? *(const float4*)&g_agg[(size_t)m * 64 + c4]
                         : *(const float4*)&x[(size_t)m * 64 + (c4 - 64)];
    __nv_bfloat16 h[4], l[4];
    split4(v, h, l);
    *(uint2*)&g_ah[(size_t)m * 128 + c4] = *(uint2*)h;
    *(uint2*)&g_al[(size_t)m * 128 + c4] = *(uint2*)l;
}
__global__ void convert_a2_kernel() {                               // [agg2(128)|h(128)] -> stride 256
    long idx = (long)blockIdx.x * blockDim.x + threadIdx.x;
    const long total = (long)N_NODES * 64;
    if (idx >= total) return;
    int m = (int)(idx >> 6);
    int c4 = ((int)idx & 63) * 4;
    float4 v = (c4 < 128) ? *(const float4*)&g_agg[(size_t)m * 128 + c4]
                          : *(const float4*)&g_h[(size_t)m * 128 + (c4 - 128)];
    __nv_bfloat16 h[4], l[4];
    split4(v, h, l);
    *(uint2*)&g_ah[(size_t)m * 256 + c4] = *(uint2*)h;
    *(uint2*)&g_al[(size_t)m * 256 + c4] = *(uint2*)l;
}
__global__ void convert_w_kernel(const float* __restrict__ Wl, const float* __restrict__ Wr, int Kh) {
    int Ktot = 2 * Kh;
    int idx = blockIdx.x * blockDim.x + threadIdx.x;
    if (idx >= 128 * Ktot) return;
    int n = idx / Ktot, k = idx % Ktot;
    float v = (k < Kh) ? Wl[(size_t)n * Kh + k] : Wr[(size_t)n * Kh + (k - Kh)];
    __nv_bfloat16 h = __float2bfloat16(v);
    __nv_bfloat16 l = __float2bfloat16(v - __bfloat162float(h));
    g_wh[idx] = h;
    g_wlo[idx] = l;
}

// ==================== mma.sync GEMM: out = act([Agg|X] @ W'^T + b) ====================
// CTA tile 128x128, BK=32 chunks in static smem (80B row stride: conflict-free
// ldmatrix, no swizzle). 8 warps, warp tile m32 x n64. 3-term bf16 split.
template <int KT, bool RELU, int LAYER>
__global__ __launch_bounds__(256) void gemm_mma_kernel(
    const float* __restrict__ bias, float* __restrict__ out_ext)
{
    constexpr int BK = 32;
    constexpr int RS = 40;   // row stride in bf16 (80 bytes = 16*5: bank-cycle coprime)
    __shared__ __align__(16) __nv_bfloat16 sAh[128 * RS];
    __shared__ __align__(16) __nv_bfloat16 sAl[128 * RS];
    __shared__ __align__(16) __nv_bfloat16 sBh[128 * RS];
    __shared__ __align__(16) __nv_bfloat16 sBl[128 * RS];

    const int tid = threadIdx.x, lane = tid & 31, wid = tid >> 5;
    const int row0 = blockIdx.x * 128;
    const int valid = min(128, N_NODES - row0);
    float* outp = (LAYER == 1) ? g_h : out_ext;

    const int wr = wid & 3;          // m offset = wr*32
    const int wc = wid >> 2;         // n offset = wc*64

    float c[2][8][4];
#pragma unroll
    for (int mi = 0; mi < 2; mi++)
#pragma unroll
        for (int ni = 0; ni < 8; ni++)
#pragma unroll
            for (int q = 0; q < 4; q++) c[mi][ni][q] = 0.f;

    const uint32_t sa  = smem_u32(sAh);
    const uint32_t sal = smem_u32(sAl);
    const uint32_t sb  = smem_u32(sBh);
    const uint32_t sbl = smem_u32(sBl);

    // ldmatrix lane->address components
    const int a_m = ((lane >> 3) & 1) * 8 + (lane & 7);  // row within m16 tile
    const int a_u = (lane >> 4);                          // 16B unit (k half)
    const int b_n = ((lane >> 4) << 3) + (lane & 7);      // row within n16 group
    const int b_u = ((lane >> 3) & 1);                    // 16B unit (k half)

    const int ld_r = tid >> 2;        // load: row
    const int ld_u = tid & 3;         // load: 16B unit within BK=32 (64B)

    for (int kc = 0; kc < KT / BK; kc++) {
#pragma unroll
        for (int it = 0; it < 2; it++) {
            int r = ld_r + it * 64;
            uint4 vh = make_uint4(0, 0, 0, 0), vl = make_uint4(0, 0, 0, 0);
            if (r < valid) {
                size_t go = (size_t)(row0 + r) * KT + kc * BK + ld_u * 8;
                vh = *(const uint4*)&g_ah[go];
                vl = *(const uint4*)&g_al[go];
            }
            *(uint4*)&sAh[r * RS + ld_u * 8] = vh;
            *(uint4*)&sAl[r * RS + ld_u * 8] = vl;
            size_t gw = (size_t)r * KT + kc * BK + ld_u * 8;
            *(uint4*)&sBh[r * RS + ld_u * 8] = *(const uint4*)&g_wh[gw];
            *(uint4*)&sBl[r * RS + ld_u * 8] = *(const uint4*)&g_wlo[gw];
        }
        __syncthreads();

#pragma unroll
        for (int ks = 0; ks < 2; ks++) {
            uint32_t ah[2][4], alr[2][4], bh[8][2], bl[8][2];
#pragma unroll
            for (int mi = 0; mi < 2; mi++) {
                int rr = wr * 32 + mi * 16 + a_m;
                uint32_t off = (uint32_t)(rr * RS + (ks * 2 + a_u) * 8) * 2;
                LDSM_X4(ah[mi][0], ah[mi][1], ah[mi][2], ah[mi][3], sa + off);
                LDSM_X4(alr[mi][0], alr[mi][1], alr[mi][2], alr[mi][3], sal + off);
            }
#pragma unroll
            for (int nj = 0; nj < 4; nj++) {
                int nr = wc * 64 + nj * 16 + b_n;
                uint32_t off = (uint32_t)(nr * RS + (ks * 2 + b_u) * 8) * 2;
                LDSM_X4(bh[nj * 2][0], bh[nj * 2][1], bh[nj * 2 + 1][0], bh[nj * 2 + 1][1], sb + off);
                LDSM_X4(bl[nj * 2][0], bl[nj * 2][1], bl[nj * 2 + 1][0], bl[nj * 2 + 1][1], sbl + off);
            }
#pragma unroll
            for (int mi = 0; mi < 2; mi++)
#pragma unroll
                for (int ni = 0; ni < 8; ni++) {
                    MMA16816(c[mi][ni], ah[mi], bh[ni]);
                    MMA16816(c[mi][ni], ah[mi], bl[ni]);
                    MMA16816(c[mi][ni], alr[mi], bh[ni]);
                }
        }
        __syncthreads();
    }

    // ---- epilogue: bias + (relu) + direct global stores ----
    const int g = lane >> 2, tg = lane & 3;
#pragma unroll
    for (int ni = 0; ni < 8; ni++) {
        int col = wc * 64 + ni * 8 + tg * 2;
        float2 bv = *(const float2*)&bias[col];
#pragma unroll
        for (int mi = 0; mi < 2; mi++) {
            int r0 = wr * 32 + mi * 16 + g;
            float v0 = c[mi][ni][0] + bv.x;
            float v1 = c[mi][ni][1] + bv.y;
            float v2 = c[mi][ni][2] + bv.x;
            float v3 = c[mi][ni][3] + bv.y;
            if (RELU) {
                v0 = fmaxf(v0, 0.f); v1 = fmaxf(v1, 0.f);
                v2 = fmaxf(v2, 0.f); v3 = fmaxf(v3, 0.f);
            }
            if (r0 < valid) {
                float2 o; o.x = v0; o.y = v1;
                *(float2*)&outp[(size_t)(row0 + r0) * 128 + col] = o;
            }
            if (r0 + 8 < valid) {
                float2 o; o.x = v2; o.y = v3;
                *(float2*)&outp[(size_t)(row0 + r0 + 8) * 128 + col] = o;
            }
        }
    }
}

// ==================== entry point ====================
extern "C" void kernel_launch(void* const* d_in, const int* in_sizes, int n_in,
                              void* d_out, int out_size)
{
    (void)n_in; (void)out_size;
    const float* x   = (const float*)d_in[0];
    const void*  ei  = d_in[1];
    const float* W1l = (const float*)d_in[2];
    const float* W1r = (const float*)d_in[3];
    const float* b1  = (const float*)d_in[4];
    const float* W2l = (const float*)d_in[5];
    const float* W2r = (const float*)d_in[6];
    const float* b2  = (const float*)d_in[7];
    float*       out = (float*)d_out;

    int E = in_sizes[1] / 2;
    if (E > E_MAX) E = E_MAX;

    // CSR build
    detect_kernel<<<1, 32>>>((const int*)ei, in_sizes[1]);
    zero_deg_kernel<<<(N_NODES + 255) / 256, 256>>>();
    hist_kernel<<<(E + 255) / 256, 256>>>(ei, E);
    scan_part_kernel<<<NPART, 1024>>>();
    scan_part2_kernel<<<1, 128>>>();
    scan_add_kernel<<<NPART, 1024>>>();
    scatter_kernel<<<(E + 255) / 256, 256>>>(ei, E);

    const int agg_blocks  = (N_NODES * 32 + 255) / 256;   // warp per node
    const int gemm_blocks = (N_NODES + 127) / 128;        // 782

    // layer 1
    agg1_kernel<<<agg_blocks, 256>>>(x);
    convert_a1_kernel<<<(N_NODES * 32 + 255) / 256, 256>>>(x);
    convert_w_kernel<<<(128 * 128 + 255) / 256, 256>>>(W1l, W1r, 64);
    gemm_mma_kernel<128, true, 1><<<gemm_blocks, 256>>>(b1, nullptr);

    // layer 2
    agg2_kernel<<<agg_blocks, 256>>>();
    convert_a2_kernel<<<(N_NODES * 64 + 255) / 256, 256>>>();
    convert_w_kernel<<<(128 * 256 + 255) / 256, 256>>>(W2l, W2r, 128);
    gemm_mma_kernel<256, false, 2><<<gemm_blocks, 256>>>(b2, out);
}

// round 5
// speedup vs baseline: 1.5879x; 1.0252x over previous
#include <cuda_runtime.h>
#include <cuda_bf16.h>
#include <cstdint>

#define N_NODES 100000
#define E_MAX   1600000
#define NPART   98          // ceil(100000/1024)

// ---------------- device scratch (static; no dynamic allocation) ----------------
__device__ int   g_is64;
__device__ int   g_deg[N_NODES];
__device__ int   g_offs[N_NODES + 1];
__device__ int   g_cursor[N_NODES];
__device__ int   g_part[NPART];
__device__ int   g_src_sorted[E_MAX];
__device__ float g_h[(size_t)N_NODES * 128];
// bf16 split A operands (per layer: A = [agg | x_or_h])
__device__ __nv_bfloat16 g_a1h[(size_t)N_NODES * 128];
__device__ __nv_bfloat16 g_a1l[(size_t)N_NODES * 128];
__device__ __nv_bfloat16 g_a2h[(size_t)N_NODES * 256];
__device__ __nv_bfloat16 g_a2l[(size_t)N_NODES * 256];
__device__ __nv_bfloat16 g_w1h[128 * 128];
__device__ __nv_bfloat16 g_w1l[128 * 128];
__device__ __nv_bfloat16 g_w2h[128 * 256];
__device__ __nv_bfloat16 g_w2l[128 * 256];

// ==================== PTX helpers (family-portable) ====================
__device__ __forceinline__ uint32_t smem_u32(const void* p) {
    uint32_t a;
    asm("{ .reg .u64 t; cvta.to.shared.u64 t, %1; cvt.u32.u64 %0, t; }" : "=r"(a) : "l"(p));
    return a;
}
#define LDSM_X4(r0, r1, r2, r3, addr)                                           \
    asm volatile("ldmatrix.sync.aligned.m8n8.x4.shared.b16 {%0,%1,%2,%3}, [%4];" \
                 : "=r"(r0), "=r"(r1), "=r"(r2), "=r"(r3) : "r"(addr))
#define MMA16816(c, a, b)                                                        \
    asm volatile("mma.sync.aligned.m16n8k16.row.col.f32.bf16.bf16.f32 "          \
                 "{%0,%1,%2,%3}, {%4,%5,%6,%7}, {%8,%9}, {%0,%1,%2,%3};"         \
                 : "+f"((c)[0]), "+f"((c)[1]), "+f"((c)[2]), "+f"((c)[3])        \
                 : "r"((a)[0]), "r"((a)[1]), "r"((a)[2]), "r"((a)[3]),           \
                   "r"((b)[0]), "r"((b)[1]))
__device__ __forceinline__ void cp16(uint32_t dst, const void* src) {
    asm volatile("cp.async.cg.shared.global [%0], [%1], 16;" :: "r"(dst), "l"(src));
}
#define CP_COMMIT() asm volatile("cp.async.commit_group;" ::: "memory")
#define CP_WAIT1()  asm volatile("cp.async.wait_group 1;" ::: "memory")
#define CP_WAIT0()  asm volatile("cp.async.wait_group 0;" ::: "memory")

__device__ __forceinline__ uint32_t pack_hi(float v0, float v1, float& r0, float& r1) {
    __nv_bfloat16 h0 = __float2bfloat16(v0), h1 = __float2bfloat16(v1);
    r0 = v0 - __bfloat162float(h0);
    r1 = v1 - __bfloat162float(h1);
    return ((uint32_t)__bfloat16_as_ushort(h1) << 16) | __bfloat16_as_ushort(h0);
}
__device__ __forceinline__ uint32_t pack_bf(float v0, float v1) {
    return ((uint32_t)__bfloat16_as_ushort(__float2bfloat16(v1)) << 16) |
           __bfloat16_as_ushort(__float2bfloat16(v0));
}

// ==================== edge dtype detection ====================
__global__ void detect_kernel(const int* __restrict__ ei32, int n_words) {
    int lane = threadIdx.x;
    int idx = 1 + 2 * lane;
    int z = (idx < n_words && ei32[idx] == 0) ? 1 : 0;
    unsigned m = __ballot_sync(0xffffffffu, z);
    if (lane == 0) g_is64 = (__popc(m) > 24) ? 1 : 0;
}

// ==================== CSR build ====================
__global__ void zero_deg_kernel() {
    int i = blockIdx.x * blockDim.x + threadIdx.x;
    if (i < N_NODES) g_deg[i] = 0;
}
__device__ __forceinline__ int load_idx(const void* ei, size_t pos) {
    if (g_is64) return (int)((const long long*)ei)[pos];
    return ((const int*)ei)[pos];
}
__global__ void hist_kernel(const void* __restrict__ ei, int E) {
    int e = blockIdx.x * blockDim.x + threadIdx.x;
    if (e < E) {
        int d = load_idx(ei, (size_t)E + e);
        if ((unsigned)d < (unsigned)N_NODES) atomicAdd(&g_deg[d], 1);
    }
}
__global__ void scan_part_kernel() {
    __shared__ int s_woff[32];
    int tid = threadIdx.x, lane = tid & 31, wid = tid >> 5;
    int i = blockIdx.x * 1024 + tid;
    int v = (i < N_NODES) ? g_deg[i] : 0;
    int inc = v;
#pragma unroll
    for (int o = 1; o < 32; o <<= 1) {
        int t = __shfl_up_sync(0xffffffffu, inc, o);
        if (lane >= o) inc += t;
    }
    if (lane == 31) s_woff[wid] = inc;
    __syncthreads();
    if (wid == 0) {
        int ws = s_woff[lane];
        int wi = ws;
#pragma unroll
        for (int o = 1; o < 32; o <<= 1) {
            int t = __shfl_up_sync(0xffffffffu, wi, o);
            if (lane >= o) wi += t;
        }
        s_woff[lane] = wi - ws;
    }
    __syncthreads();
    int excl = s_woff[wid] + inc - v;
    if (i < N_NODES) g_offs[i] = excl;
    if (tid == 1023) g_part[blockIdx.x] = excl + v;
}
__global__ void scan_part2_kernel() {
    __shared__ int sw[4];
    int t = threadIdx.x, lane = t & 31, w = t >> 5;
    int v = (t < NPART) ? g_part[t] : 0;
    int inc = v;
#pragma unroll
    for (int o = 1; o < 32; o <<= 1) {
        int x = __shfl_up_sync(0xffffffffu, inc, o);
        if (lane >= o) inc += x;
    }
    if (lane == 31) sw[w] = inc;
    __syncthreads();
    int woff = 0;
    for (int k = 0; k < w; k++) woff += sw[k];
    int excl = woff + inc - v;
    if (t < NPART) g_part[t] = excl;
    if (t == NPART - 1) g_offs[N_NODES] = excl + v;
}
__global__ void scan_add_kernel() {
    int i = blockIdx.x * 1024 + threadIdx.x;
    if (i < N_NODES) {
        int o = g_offs[i] + g_part[blockIdx.x];
        g_offs[i] = o;
        g_cursor[i] = o;
    }
}
__global__ void scatter_kernel(const void* __restrict__ ei, int E) {
    int e = blockIdx.x * blockDim.x + threadIdx.x;
    if (e < E) {
        int d = load_idx(ei, (size_t)E + e);
        int s = load_idx(ei, (size_t)e);
        if ((unsigned)d < (unsigned)N_NODES && (unsigned)s < (unsigned)N_NODES) {
            int p = atomicAdd(&g_cursor[d], 1);
            g_src_sorted[p] = s;
        }
    }
}

// ==================== fused aggregation + bf16 split ====================
// layer 1: mean(x neighbors) -> A1 cols 0..63 ; x row -> A1 cols 64..127
__global__ void agg1_kernel(const float* __restrict__ x) {
    int w = (blockIdx.x * blockDim.x + threadIdx.x) >> 5;
    if (w >= N_NODES) return;
    int lane = threadIdx.x & 31;
    int beg = g_offs[w], end = g_offs[w + 1];
    float inv = 1.0f / (float)max(end - beg, 1);
    float ax = 0.f, ay = 0.f;
    for (int eb = beg; eb < end; eb += 32) {
        int n = min(32, end - eb);
        int s = (lane < n) ? g_src_sorted[eb + lane] : 0;
        for (int t = 0; t < n; t++) {
            int ss = __shfl_sync(0xffffffffu, s, t);
            float2 v = *(const float2*)&x[(size_t)ss * 64 + lane * 2];
            ax += v.x; ay += v.y;
        }
    }
    ax *= inv; ay *= inv;
    float r0, r1;
    size_t base = (size_t)w * 128 + lane * 2;
    uint32_t hp = pack_hi(ax, ay, r0, r1);
    *(uint32_t*)&g_a1h[base] = hp;
    *(uint32_t*)&g_a1l[base] = pack_bf(r0, r1);
    // x row conversion (cols 64..127)
    float2 xv = *(const float2*)&x[(size_t)w * 64 + lane * 2];
    hp = pack_hi(xv.x, xv.y, r0, r1);
    *(uint32_t*)&g_a1h[base + 64] = hp;
    *(uint32_t*)&g_a1l[base + 64] = pack_bf(r0, r1);
}
// layer 2: mean(h neighbors) -> A2 cols 0..127 (h row part written by gemm1 epilogue)
__global__ void agg2_kernel() {
    int w = (blockIdx.x * blockDim.x + threadIdx.x) >> 5;
    if (w >= N_NODES) return;
    int lane = threadIdx.x & 31;
    int beg = g_offs[w], end = g_offs[w + 1];
    float inv = 1.0f / (float)max(end - beg, 1);
    float ax = 0.f, ay = 0.f, az = 0.f, aw = 0.f;
    for (int eb = beg; eb < end; eb += 32) {
        int n = min(32, end - eb);
        int s = (lane < n) ? g_src_sorted[eb + lane] : 0;
        for (int t = 0; t < n; t++) {
            int ss = __shfl_sync(0xffffffffu, s, t);
            float4 v = *(const float4*)&g_h[(size_t)ss * 128 + lane * 4];
            ax += v.x; ay += v.y; az += v.z; aw += v.w;
        }
    }
    ax *= inv; ay *= inv; az *= inv; aw *= inv;
    float r0, r1, r2, r3;
    uint32_t h0 = pack_hi(ax, ay, r0, r1);
    uint32_t h1 = pack_hi(az, aw, r2, r3);
    size_t base = (size_t)w * 256 + lane * 4;
    uint2 hv; hv.x = h0; hv.y = h1;
    uint2 lv; lv.x = pack_bf(r0, r1); lv.y = pack_bf(r2, r3);
    *(uint2*)&g_a2h[base] = hv;
    *(uint2*)&g_a2l[base] = lv;
}

// ==================== weight conversion (both layers, one launch) ====================
__global__ void convert_w_kernel(const float* __restrict__ W1l, const float* __restrict__ W1r,
                                 const float* __restrict__ W2l, const float* __restrict__ W2r) {
    int idx = blockIdx.x * blockDim.x + threadIdx.x;
    if (idx < 128 * 128) {               // layer 1: Ktot = 128, Kh = 64
        int n = idx >> 7, k = idx & 127;
        float v = (k < 64) ? W1l[n * 64 + k] : W1r[n * 64 + (k - 64)];
        __nv_bfloat16 h = __float2bfloat16(v);
        g_w1h[idx] = h;
        g_w1l[idx] = __float2bfloat16(v - __bfloat162float(h));
    } else if (idx < 128 * 128 + 128 * 256) {   // layer 2: Ktot = 256, Kh = 128
        int j = idx - 128 * 128;
        int n = j >> 8, k = j & 255;
        float v = (k < 128) ? W2l[n * 128 + k] : W2r[n * 128 + (k - 128)];
        __nv_bfloat16 h = __float2bfloat16(v);
        g_w2h[j] = h;
        g_w2l[j] = __float2bfloat16(v - __bfloat162float(h));
    }
}

// ==================== cp.async pipelined mma.sync GEMM ====================
// CTA 128x128, BK=16, 2-stage cp.async double buffer. Row stride 24 bf16 (48B:
// 16B-aligned for cp.async AND ldmatrix conflict-free: (12r+4u) mod 32 distinct).
// 8 warps, warp tile m32 x n64. 3-term split: AhBh + AhBl + AlBh.
template <int KT, bool RELU, int LAYER>
__global__ __launch_bounds__(256) void gemm_mma_kernel(
    const float* __restrict__ bias, float* __restrict__ out_ext)
{
    constexpr int NCH = KT / 16;
    constexpr int RS = 24;                 // bf16 elements per row (48 B)
    constexpr uint32_t ARR_B = 128 * RS * 2;      // 6144 B per array
    constexpr uint32_t STG_B = 4 * ARR_B;         // 24576 B per stage
    __shared__ __align__(16) __nv_bfloat16 sbuf[2][4][128 * RS];   // 48 KB exactly

    const __nv_bfloat16* Ah = (LAYER == 1) ? g_a1h : g_a2h;
    const __nv_bfloat16* Al = (LAYER == 1) ? g_a1l : g_a2l;
    const __nv_bfloat16* Wh = (LAYER == 1) ? g_w1h : g_w2h;
    const __nv_bfloat16* Wl = (LAYER == 1) ? g_w1l : g_w2l;

    const int tid = threadIdx.x, lane = tid & 31, wid = tid >> 5;
    const int row0 = blockIdx.x * 128;
    const int valid = min(128, N_NODES - row0);
    const int wr = wid & 3, wc = wid >> 2;

    float c[2][8][4];
#pragma unroll
    for (int mi = 0; mi < 2; mi++)
#pragma unroll
        for (int ni = 0; ni < 8; ni++)
#pragma unroll
            for (int q = 0; q < 4; q++) c[mi][ni][q] = 0.f;

    const uint32_t sb0 = smem_u32(sbuf);

    // cp.async load mapping: thread -> (row, 16B-unit)
    const int ld_r = tid >> 1, ld_u = tid & 1;
    const int ar = min(row0 + ld_r, N_NODES - 1);    // clamp (extra rows discarded)
    const size_t goA = (size_t)ar * KT + ld_u * 8;
    const size_t goW = (size_t)ld_r * KT + ld_u * 8;
    const uint32_t dst_ru = (uint32_t)(ld_r * RS + ld_u * 8) * 2;

    // ldmatrix lane->address components (identical fragment math to round 4)
    const int a_m = ((lane >> 3) & 1) * 8 + (lane & 7);
    const int a_u = (lane >> 4);
    const int b_n = ((lane >> 4) << 3) + (lane & 7);
    const int b_u = ((lane >> 3) & 1);

    // prologue: issue chunk 0 into stage 0
    {
        uint32_t d = sb0 + dst_ru;
        cp16(d + 0 * ARR_B, &Ah[goA]);
        cp16(d + 1 * ARR_B, &Al[goA]);
        cp16(d + 2 * ARR_B, &Wh[goW]);
        cp16(d + 3 * ARR_B, &Wl[goW]);
        CP_COMMIT();
    }

    for (int kc = 0; kc < NCH; kc++) {
        if (kc + 1 < NCH) {
            uint32_t d = sb0 + ((kc + 1) & 1) * STG_B + dst_ru;
            size_t ko = (size_t)(kc + 1) * 16;
            cp16(d + 0 * ARR_B, &Ah[goA + ko]);
            cp16(d + 1 * ARR_B, &Al[goA + ko]);
            cp16(d + 2 * ARR_B, &Wh[goW + ko]);
            cp16(d + 3 * ARR_B, &Wl[goW + ko]);
            CP_COMMIT();
            CP_WAIT1();
        } else {
            CP_WAIT0();
        }
        __syncthreads();

        const uint32_t sa  = sb0 + (kc & 1) * STG_B;
        const uint32_t sal = sa + 1 * ARR_B;
        const uint32_t sbh = sa + 2 * ARR_B;
        const uint32_t sbl = sa + 3 * ARR_B;

        uint32_t ah[2][4], alr[2][4], bh[8][2], bl[8][2];
#pragma unroll
        for (int mi = 0; mi < 2; mi++) {
            int rr = wr * 32 + mi * 16 + a_m;
            uint32_t off = (uint32_t)(rr * RS + a_u * 8) * 2;
            LDSM_X4(ah[mi][0], ah[mi][1], ah[mi][2], ah[mi][3], sa + off);
            LDSM_X4(alr[mi][0], alr[mi][1], alr[mi][2], alr[mi][3], sal + off);
        }
#pragma unroll
        for (int nj = 0; nj < 4; nj++) {
            int nr = wc * 64 + nj * 16 + b_n;
            uint32_t off = (uint32_t)(nr * RS + b_u * 8) * 2;
            LDSM_X4(bh[nj * 2][0], bh[nj * 2][1], bh[nj * 2 + 1][0], bh[nj * 2 + 1][1], sbh + off);
            LDSM_X4(bl[nj * 2][0], bl[nj * 2][1], bl[nj * 2 + 1][0], bl[nj * 2 + 1][1], sbl + off);
        }
#pragma unroll
        for (int mi = 0; mi < 2; mi++)
#pragma unroll
            for (int ni = 0; ni < 8; ni++) {
                MMA16816(c[mi][ni], ah[mi], bh[ni]);
                MMA16816(c[mi][ni], ah[mi], bl[ni]);
                MMA16816(c[mi][ni], alr[mi], bh[ni]);
            }
        __syncthreads();
    }

    // ---- epilogue ----
    const int g = lane >> 2, tg = lane & 3;
#pragma unroll
    for (int ni = 0; ni < 8; ni++) {
        int col = wc * 64 + ni * 8 + tg * 2;
        float2 bv = *(const float2*)&bias[col];
#pragma unroll
        for (int mi = 0; mi < 2; mi++) {
            int rl = wr * 32 + mi * 16 + g;
#pragma unroll
            for (int hrow = 0; hrow < 2; hrow++) {
                int r = rl + hrow * 8;
                if (r >= valid) continue;
                float v0 = c[mi][ni][hrow * 2 + 0] + bv.x;
                float v1 = c[mi][ni][hrow * 2 + 1] + bv.y;
                if (RELU) { v0 = fmaxf(v0, 0.f); v1 = fmaxf(v1, 0.f); }
                size_t grow = (size_t)(row0 + r);
                if (LAYER == 1) {
                    float2 o; o.x = v0; o.y = v1;
                    *(float2*)&g_h[grow * 128 + col] = o;
                    float r0, r1;
                    uint32_t hp = pack_hi(v0, v1, r0, r1);     // A2 X-part
                    *(uint32_t*)&g_a2h[grow * 256 + 128 + col] = hp;
                    *(uint32_t*)&g_a2l[grow * 256 + 128 + col] = pack_bf(r0, r1);
                } else {
                    float2 o; o.x = v0; o.y = v1;
                    *(float2*)&out_ext[grow * 128 + col] = o;
                }
            }
        }
    }
}

// ==================== entry point ====================
extern "C" void kernel_launch(void* const* d_in, const int* in_sizes, int n_in,
                              void* d_out, int out_size)
{
    (void)n_in; (void)out_size;
    const float* x   = (const float*)d_in[0];
    const void*  ei  = d_in[1];
    const float* W1l = (const float*)d_in[2];
    const float* W1r = (const float*)d_in[3];
    const float* b1  = (const float*)d_in[4];
    const float* W2l = (const float*)d_in[5];
    const float* W2r = (const float*)d_in[6];
    const float* b2  = (const float*)d_in[7];
    float*       out = (float*)d_out;

    int E = in_sizes[1] / 2;
    if (E > E_MAX) E = E_MAX;

    // CSR build
    detect_kernel<<<1, 32>>>((const int*)ei, in_sizes[1]);
    zero_deg_kernel<<<(N_NODES + 255) / 256, 256>>>();
    hist_kernel<<<(E + 255) / 256, 256>>>(ei, E);
    scan_part_kernel<<<NPART, 1024>>>();
    scan_part2_kernel<<<1, 128>>>();
    scan_add_kernel<<<NPART, 1024>>>();
    scatter_kernel<<<(E + 255) / 256, 256>>>(ei, E);

    // weights (both layers)
    convert_w_kernel<<<(128 * 128 + 128 * 256 + 255) / 256, 256>>>(W1l, W1r, W2l, W2r);

    const int agg_blocks  = (N_NODES * 32 + 255) / 256;   // warp per node
    const int gemm_blocks = (N_NODES + 127) / 128;        // 782

    agg1_kernel<<<agg_blocks, 256>>>(x);
    gemm_mma_kernel<128, true, 1><<<gemm_blocks, 256>>>(b1, nullptr);
    agg2_kernel<<<agg_blocks, 256>>>();
    gemm_mma_kernel<256, false, 2><<<gemm_blocks, 256>>>(b2, out);
}